// round 15
// baseline (speedup 1.0000x reference)
#include <cuda_runtime.h>
#include <cuda_fp16.h>
#include <cstdint>
#include <cstddef>

// ---------------------------------------------------------------------------
// Sigmoid attention, algebraically refactored (R8-R14) + R15:
//   s[n,m] = y_n·x_m + u·x_m + w·x_n + c0,  y = x·(Wq^T Wk)  (O_CH contracts early)
// R15: uw_reduce launch deleted. u/w/c0 computed inside prep_weights (z=3
// slice, independent inputs). Split-K M GEMM reduces its own partials via the
// last-CTA atomic-counter pattern (EPI==4 epilogue, counters zeroed per replay
// by prep_weights -> graph-safe, fixed reduce order -> deterministic).
// Launch chain: prep -> xpose -> M(fused reduce) -> dual{v,y,rb/cb} -> alpha -> out.
// Hot GEMM mainloop unchanged (128x128 CTA, 4 warps of 64x64, 3-stage
// cp.async, ldmatrix.x4 double-buffered fragments, 2 CTA/SM).
// ---------------------------------------------------------------------------

#define BM 128
#define BN 128
#define STAGE 32768               // A tile 16KB + B tile 16KB
#define NSTAGE 3
#define SMEM_TOTAL (NSTAGE * STAGE)

// ------------------------------- scratch ------------------------------------
#define AL16 __align__(16)
static __device__ AL16 __half g_xT [(size_t)4*4096*512];    // xT[b][n][c]
static __device__ AL16 __half g_WqT[512*1024];              // Wq^T[c][o] (o pad 1000->1024)
static __device__ AL16 __half g_WkT[512*1024];              // Wk^T[c][o]
static __device__ AL16 __half g_Wv [512*512];               // Wv[c][c'] fp16
static __device__ AL16 float  g_Mp [4*512*512];             // split-K partials (fp32)
static __device__ AL16 __half g_M  [512*512];               // Mkq = Wk^T·Wq
static __device__ AL16 __half g_y  [(size_t)4*4096*512];    // y[b][n][c']
static __device__ AL16 __half g_v  [(size_t)4*512*4096];    // v[b][c][n]
static __device__ AL16 __half g_a  [(size_t)4*4096*4096];   // aT[b][m][n]
static __device__ float g_bv[512];
static __device__ float g_u[512], g_w[512], g_c0[1];
static __device__ float g_rb[4*4096], g_cb[4*4096];         // row/col bias for alpha
static __device__ int   g_cnt[16];                          // split-K tile counters

// ------------------------------- helpers ------------------------------------
__device__ __forceinline__ void ldsm_x4(uint32_t& r0, uint32_t& r1, uint32_t& r2, uint32_t& r3,
                                        uint32_t addr) {
    asm volatile("ldmatrix.sync.aligned.m8n8.x4.shared.b16 {%0,%1,%2,%3}, [%4];"
                 : "=r"(r0), "=r"(r1), "=r"(r2), "=r"(r3) : "r"(addr));
}

__device__ __forceinline__ void mma_fp16(float* d, const uint32_t* a, const uint32_t* b) {
    asm volatile(
        "mma.sync.aligned.m16n8k16.row.col.f32.f16.f16.f32 "
        "{%0,%1,%2,%3}, {%4,%5,%6,%7}, {%8,%9}, {%0,%1,%2,%3};\n"
        : "+f"(d[0]), "+f"(d[1]), "+f"(d[2]), "+f"(d[3])
        : "r"(a[0]), "r"(a[1]), "r"(a[2]), "r"(a[3]), "r"(b[0]), "r"(b[1]));
}

__device__ __forceinline__ float sigmoid_fast(float x) {
    float t;
    asm("tanh.approx.f32 %0, %1;" : "=f"(t) : "f"(0.5f * x));
    return 0.5f + 0.5f * t;
}

// ---------------------------- prep kernels ----------------------------------
// x[b][c][n] fp32 -> xT[b][n][c] fp16
__global__ void xpose_h(const float* __restrict__ x, __half* __restrict__ xT) {
    __shared__ float t[32][33];
    const int b = blockIdx.z;
    const float* xb = x + (size_t)b * 512 * 4096;
    const int n0 = blockIdx.x * 32, c0 = blockIdx.y * 32;
    const int tx = threadIdx.x, ty0 = threadIdx.y;
#pragma unroll
    for (int i = 0; i < 4; i++) {
        int ty = ty0 + i * 8;
        t[ty][tx] = xb[(size_t)(c0 + ty) * 4096 + n0 + tx];
    }
    __syncthreads();
    const size_t ob = (size_t)b * 4096 * 512;
#pragma unroll
    for (int i = 0; i < 4; i++) {
        int ty = ty0 + i * 8;
        xT[ob + (size_t)(n0 + ty) * 512 + c0 + tx] = __float2half_rn(t[tx][ty]);
    }
}

// merged weight prep: z=0 -> Wq^T ; z=1 -> Wk^T ; z=2 -> Wv fp16 + bv + cnt=0 ;
//                     z=3 -> u/w/c0 (from original fp32 weights, hidden slice)
__global__ void prep_weights(const float* __restrict__ Wq, const float* __restrict__ Wk,
                             const float* __restrict__ Wv, const float* __restrict__ bv,
                             const float* __restrict__ bq, const float* __restrict__ bk,
                             __half* __restrict__ WqT, __half* __restrict__ WkT,
                             __half* __restrict__ Wvh, float* __restrict__ bvp,
                             float* __restrict__ u, float* __restrict__ w,
                             float* __restrict__ c0) {
    const int z = blockIdx.z;
    if (z < 2) {
        __shared__ float t[32][33];
        const float* W = z ? Wk : Wq;
        __half* WT = z ? WkT : WqT;
        const int r0 = blockIdx.x * 32, c0_ = blockIdx.y * 32;
        const int tx = threadIdx.x, ty0 = threadIdx.y;
#pragma unroll
        for (int i = 0; i < 4; i++) {
            int ty = ty0 + i * 8;
            int r = r0 + ty;
            t[ty][tx] = (r < 1000) ? W[(size_t)r * 512 + c0_ + tx] : 0.0f;
        }
        __syncthreads();
#pragma unroll
        for (int i = 0; i < 4; i++) {
            int ty = ty0 + i * 8;
            WT[(size_t)(c0_ + ty) * 1024 + r0 + tx] = __float2half_rn(t[tx][ty]);
        }
    } else if (z == 2) {
        // 512 blocks x 256 threads x 2 elements = 262144 = full Wv coverage
        int idx = (blockIdx.y * 32 + blockIdx.x) * 256 + threadIdx.y * 32 + threadIdx.x;
        Wvh[idx]          = __float2half_rn(Wv[idx]);
        Wvh[idx + 131072] = __float2half_rn(Wv[idx + 131072]);
        if (idx < 512) bvp[idx] = bv[idx];
        if (idx < 16) g_cnt[idx] = 0;            // zero split-K counters (per replay)
    } else {
        // z == 3: u[c] = sum_o Wk[o][c]*bq[o] ; w[c] = sum_o Wq[o][c]*bk[o] ; c0 = bq.bk
        const int tid = threadIdx.y * 32 + threadIdx.x;   // 0..255
        if (blockIdx.y == 0) {
            __shared__ float su[16][16], sw[16][16];
            const int tx = tid & 15;            // channel-within-block
            const int og = tid >> 4;            // o-group 0..15
            const int c = blockIdx.x * 16 + tx;
            float au = 0.f, aw = 0.f;
            for (int o = og; o < 1000; o += 16) {
                au += Wk[(size_t)o * 512 + c] * bq[o];
                aw += Wq[(size_t)o * 512 + c] * bk[o];
            }
            su[og][tx] = au; sw[og][tx] = aw;
            __syncthreads();
            if (og == 0) {
                float a0 = 0.f, w0 = 0.f;
#pragma unroll
                for (int j = 0; j < 16; j++) { a0 += su[j][tx]; w0 += sw[j][tx]; }
                u[c] = a0; w[c] = w0;
            }
        } else if (blockIdx.y == 1 && blockIdx.x == 0) {
            if (tid < 32) {
                float s = 0.f;
                for (int o = tid; o < 1000; o += 32) s += bq[o] * bk[o];
#pragma unroll
                for (int off = 16; off > 0; off >>= 1) s += __shfl_xor_sync(0xFFFFFFFF, s, off);
                if (tid == 0) *c0 = s;
            }
        }
    }
}

// ------------------------- GEMM mainloop (macro body) ------------------------
#define GEMM_BODY(A_, lda_, B_, ldb_, K_)                                           \
    extern __shared__ __align__(1024) char smem[];                                  \
    const uint32_t sb = (uint32_t)__cvta_generic_to_shared(smem);                   \
    const int tid  = threadIdx.x;                                                   \
    const int lane = tid & 31;                                                      \
    const int w    = tid >> 5;                                                      \
    const int wm   = (w & 1) * 64;                                                  \
    const int wn   = (w >> 1) * 64;                                                 \
    const int g    = lane >> 2;                                                     \
    const int tg   = lane & 3;                                                      \
    const int T = (K_) / 64;                                                        \
    auto load_stage = [&](int t, int s) {                                           \
        const uint32_t st = sb + (uint32_t)(s * STAGE);                             \
        const int kc = t * 64;                                                      \
_Pragma("unroll")                                                                   \
        for (int i = 0; i < 16; i++) {                                              \
            int idx = tid + i * 128;                                                \
            int isB = idx >> 10;                                                    \
            int r   = (idx & 1023) >> 3;                                            \
            int c   = idx & 7;                                                      \
            uint32_t dst = st + (uint32_t)(isB * 16384 + r * 128 + ((c ^ (r & 7)) << 4)); \
            const __half* gp = (isB ? (B_) + (size_t)(n0 + r) * (ldb_)              \
                                    : (A_) + (size_t)(m0 + r) * (lda_)) + kc + c * 8; \
            asm volatile("cp.async.cg.shared.global [%0], [%1], 16;" :: "r"(dst), "l"(gp) : "memory"); \
        }                                                                           \
        asm volatile("cp.async.commit_group;" ::: "memory");                        \
    };                                                                              \
    float acc[4][8][4];                                                             \
_Pragma("unroll")                                                                   \
    for (int i = 0; i < 4; i++)                                                     \
_Pragma("unroll")                                                                   \
        for (int j = 0; j < 8; j++)                                                 \
_Pragma("unroll")                                                                   \
            for (int r = 0; r < 4; r++) acc[i][j][r] = 0.0f;                        \
    load_stage(0, 0);                                                               \
    load_stage(1, 1);                                                               \
    const int rowA = wm + (lane & 15);                                              \
    const int hiA  = lane >> 4;                                                     \
    const int rowB = wn + ((lane >> 4) << 3) + (lane & 7);                          \
    const int hiB  = (lane >> 3) & 1;                                               \
    for (int t = 0; t < T; t++) {                                                   \
        asm volatile("cp.async.wait_group 1;" ::: "memory");                        \
        __syncthreads();                                                            \
        const uint32_t st  = sb + (uint32_t)((t % NSTAGE) * STAGE);                 \
        const uint32_t stB = st + 16384;                                            \
        uint32_t af[2][4][4], bf[2][8][2];                                          \
        auto load_frags = [&](int ks, int buf) {                                    \
_Pragma("unroll")                                                                   \
            for (int im = 0; im < 4; im++) {                                        \
                const int r = rowA + im * 16;                                       \
                const int c = (ks * 2 + hiA) ^ (r & 7);                             \
                ldsm_x4(af[buf][im][0], af[buf][im][1], af[buf][im][2], af[buf][im][3], \
                        st + (uint32_t)(r * 128 + (c << 4)));                       \
            }                                                                       \
_Pragma("unroll")                                                                   \
            for (int jn = 0; jn < 4; jn++) {                                        \
                const int r = rowB + jn * 16;                                       \
                const int c = (ks * 2 + hiB) ^ (r & 7);                             \
                ldsm_x4(bf[buf][2*jn][0], bf[buf][2*jn][1], bf[buf][2*jn+1][0], bf[buf][2*jn+1][1], \
                        stB + (uint32_t)(r * 128 + (c << 4)));                      \
            }                                                                       \
        };                                                                          \
        load_frags(0, 0);                                                           \
        if (t + 2 < T) load_stage(t + 2, (t + 2) % NSTAGE);                         \
_Pragma("unroll")                                                                   \
        for (int ks = 0; ks < 4; ks++) {                                            \
            const int cur = ks & 1;                                                 \
            if (ks < 3) load_frags(ks + 1, cur ^ 1);                                \
_Pragma("unroll")                                                                   \
            for (int im = 0; im < 4; im++)                                          \
_Pragma("unroll")                                                                   \
                for (int in = 0; in < 8; in++)                                      \
                    mma_fp16(acc[im][in], af[cur][im], bf[cur][in]);                \
        }                                                                           \
    }

// ---------------------- hot GEMM (templated epilogue) ------------------------
// EPI: 0 = fp32 store (out) ; 3 = sigmoid+biases (alpha) ;
//      4 = fp32 split-K partial + last-CTA reduce to fp16 g_M
template <int EPI>
__global__ __launch_bounds__(128, 2)
void gemm_h(const __half* __restrict__ Ag, int lda, size_t sA,
            const __half* __restrict__ Bg, int ldb, size_t sB,
            void* Dg, int ldd, size_t sD,
            const float* __restrict__ bias1, int s1,
            const float* __restrict__ bias2, int s2,
            int K) {
    const __half* A = Ag + (size_t)blockIdx.z * sA;
    const __half* B = Bg + (size_t)blockIdx.z * sB;
    const float* b1 = (EPI == 3) ? bias1 + (size_t)blockIdx.z * s1 : nullptr;
    const float* b2 = (EPI == 3) ? bias2 + (size_t)blockIdx.z * s2 : nullptr;
    const int m0 = blockIdx.y * BM;
    const int n0 = blockIdx.x * BN;

    GEMM_BODY(A, lda, B, ldb, K)

#pragma unroll
    for (int im = 0; im < 4; im++) {
        const int r0 = m0 + wm + im * 16 + g;
#pragma unroll
        for (int in = 0; in < 8; in++) {
            const int c = n0 + wn + in * 8 + 2 * tg;
#pragma unroll
            for (int h = 0; h < 2; h++) {
                const int r = r0 + h * 8;
                float vx = acc[im][in][2 * h];
                float vy = acc[im][in][2 * h + 1];
                if (EPI == 3) {
                    float bb = b1[r];
                    vx = sigmoid_fast(vx + bb + b2[c]);
                    vy = sigmoid_fast(vy + bb + b2[c + 1]);
                }
                if (EPI == 0 || EPI == 4) {
                    float* D = (float*)Dg + (size_t)blockIdx.z * sD + (size_t)r * ldd + c;
                    *reinterpret_cast<float2*>(D) = make_float2(vx, vy);
                } else {
                    __half* D = (__half*)Dg + (size_t)blockIdx.z * sD + (size_t)r * ldd + c;
                    *reinterpret_cast<__half2*>(D) = __floats2half2_rn(vx, vy);
                }
            }
        }
    }

    if (EPI == 4) {
        // last-CTA-per-tile reduces the 4 fp32 partials -> fp16 g_M
        __threadfence();
        __syncthreads();
        __shared__ int flag;
        if (tid == 0)
            flag = (atomicAdd(&g_cnt[blockIdx.y * 4 + blockIdx.x], 1) == 3);
        __syncthreads();
        if (flag) {
            const float* P = (const float*)Dg;          // Mp base
            for (int i = tid; i < 128 * 32; i += 128) { // 128 rows x 32 float4
                const int r  = i >> 5;
                const int c4 = (i & 31) << 2;
                const size_t off = (size_t)(m0 + r) * 512 + n0 + c4;
                float4 s = *reinterpret_cast<const float4*>(P + off);
#pragma unroll
                for (int p = 1; p < 4; p++) {
                    float4 t2 = *reinterpret_cast<const float4*>(P + (size_t)p * sD + off);
                    s.x += t2.x; s.y += t2.y; s.z += t2.z; s.w += t2.w;
                }
                __half2 h0 = __floats2half2_rn(s.x, s.y);
                __half2 h1 = __floats2half2_rn(s.z, s.w);
                *reinterpret_cast<uint2*>(g_M + off) =
                    make_uint2(*reinterpret_cast<uint32_t*>(&h0),
                               *reinterpret_cast<uint32_t*>(&h1));
            }
        }
    }
}

// --------- merged v/y GEMM + rb/cb slice: one launch, runtime select ---------
// grid (128, 1, 9): z<4 -> v GEMM batch z; z in [4,8) -> y GEMM batch z-4;
//                   z==8 -> rb/cb computation (hidden under the GEMM slices).
__global__ __launch_bounds__(128, 2)
void gemm_dual(const __half* __restrict__ Wvh, const __half* __restrict__ xT,
               const __half* __restrict__ Mkq,
               __half* __restrict__ v, __half* __restrict__ y,
               const float* __restrict__ bvp,
               const float* __restrict__ u_, const float* __restrict__ w_,
               const float* __restrict__ c0_,
               float* __restrict__ rb, float* __restrict__ cb) {
    const size_t sXT = (size_t)4096 * 512;
    const int z = blockIdx.z;

    if (z == 8) {
        // rb[row] = u.x_row ; cb[row] = w.x_row + c0 ; 128 blocks x 128 rows
        extern __shared__ __align__(1024) float smemf[];
        float* su = smemf;            // 512 floats
        float* sw = smemf + 512;      // 512 floats
        const int tid = threadIdx.x;
        for (int i = tid; i < 512; i += 128) { su[i] = u_[i]; sw[i] = w_[i]; }
        __syncthreads();
        const float cc0 = *c0_;
        const int lane = tid & 31;
        const int warp = tid >> 5;
        for (int i = 0; i < 32; i++) {
            const int row = blockIdx.x * 128 + warp * 32 + i;
            const uint4* xr = reinterpret_cast<const uint4*>(xT + (size_t)row * 512);
            float au = 0.f, aw = 0.f;
#pragma unroll
            for (int j = 0; j < 2; j++) {
                const int v4 = lane + j * 32;          // uint4 index, 64 per row
                uint4 p = xr[v4];
                const __half2* h2 = reinterpret_cast<const __half2*>(&p);
                const int base = v4 * 8;
#pragma unroll
                for (int q = 0; q < 4; q++) {
                    float2 f = __half22float2(h2[q]);
                    au += su[base + 2*q] * f.x + su[base + 2*q + 1] * f.y;
                    aw += sw[base + 2*q] * f.x + sw[base + 2*q + 1] * f.y;
                }
            }
#pragma unroll
            for (int off = 16; off > 0; off >>= 1) {
                au += __shfl_xor_sync(0xFFFFFFFF, au, off);
                aw += __shfl_xor_sync(0xFFFFFFFF, aw, off);
            }
            if (lane == 0) { rb[row] = au; cb[row] = aw + cc0; }
        }
        return;
    }

    const int isV = (z < 4);
    const int b = isV ? z : z - 4;
    const int id = blockIdx.x;

    const __half* A;  const __half* B;  __half* D;
    int lda, ldb, ldd, m0, n0;
    const float* b1 = nullptr;
    if (isV) {         // v[c][n'] = Wv·xT + bv : M=512, N=4096, K=512; grid 4m x 32n
        A = Wvh; lda = 512;
        B = xT + (size_t)b * sXT; ldb = 512;
        D = v + (size_t)b * ((size_t)512 * 4096); ldd = 4096;
        m0 = (id >> 5) * BM;  n0 = (id & 31) * BN;
        b1 = bvp;
    } else {           // y[n][c'] = xT·Mkq : M=4096, N=512, K=512; grid 32m x 4n
        A = xT + (size_t)b * sXT; lda = 512;
        B = Mkq; ldb = 512;
        D = y + (size_t)b * sXT; ldd = 512;
        m0 = (id >> 2) * BM;  n0 = (id & 3) * BN;
    }

    GEMM_BODY(A, lda, B, ldb, 512)

#pragma unroll
    for (int im = 0; im < 4; im++) {
        const int r0 = m0 + wm + im * 16 + g;
#pragma unroll
        for (int in = 0; in < 8; in++) {
            const int c = n0 + wn + in * 8 + 2 * tg;
#pragma unroll
            for (int h = 0; h < 2; h++) {
                const int r = r0 + h * 8;
                float vx = acc[im][in][2 * h];
                float vy = acc[im][in][2 * h + 1];
                if (isV) { float bb = b1[r]; vx += bb; vy += bb; }
                __half* Dp = D + (size_t)r * ldd + c;
                *reinterpret_cast<__half2*>(Dp) = __floats2half2_rn(vx, vy);
            }
        }
    }
}

// ------------------------------- launch -------------------------------------
extern "C" void kernel_launch(void* const* d_in, const int* in_sizes, int n_in,
                              void* d_out, int out_size) {
    (void)in_sizes; (void)n_in; (void)out_size;
    const float* x  = (const float*)d_in[0];
    const float* Wq = (const float*)d_in[1];
    const float* bq = (const float*)d_in[2];
    const float* Wk = (const float*)d_in[3];
    const float* bk = (const float*)d_in[4];
    const float* Wv = (const float*)d_in[5];
    const float* bv = (const float*)d_in[6];
    float* out = (float*)d_out;

    __half *xT,*WqT,*WkT,*Wvh,*M,*y,*v,*a;
    float *Mp,*bvp,*u,*w,*c0,*rb,*cb;
    cudaGetSymbolAddress((void**)&xT,  g_xT);
    cudaGetSymbolAddress((void**)&WqT, g_WqT);
    cudaGetSymbolAddress((void**)&WkT, g_WkT);
    cudaGetSymbolAddress((void**)&Wvh, g_Wv);
    cudaGetSymbolAddress((void**)&Mp,  g_Mp);
    cudaGetSymbolAddress((void**)&M,   g_M);
    cudaGetSymbolAddress((void**)&y,   g_y);
    cudaGetSymbolAddress((void**)&v,   g_v);
    cudaGetSymbolAddress((void**)&a,   g_a);
    cudaGetSymbolAddress((void**)&bvp, g_bv);
    cudaGetSymbolAddress((void**)&u,   g_u);
    cudaGetSymbolAddress((void**)&w,   g_w);
    cudaGetSymbolAddress((void**)&c0,  g_c0);
    cudaGetSymbolAddress((void**)&rb,  g_rb);
    cudaGetSymbolAddress((void**)&cb,  g_cb);

    cudaFuncSetAttribute(gemm_h<0>, cudaFuncAttributeMaxDynamicSharedMemorySize, SMEM_TOTAL);
    cudaFuncSetAttribute(gemm_h<3>, cudaFuncAttributeMaxDynamicSharedMemorySize, SMEM_TOTAL);
    cudaFuncSetAttribute(gemm_h<4>, cudaFuncAttributeMaxDynamicSharedMemorySize, SMEM_TOTAL);
    cudaFuncSetAttribute(gemm_dual, cudaFuncAttributeMaxDynamicSharedMemorySize, SMEM_TOTAL);

    // ---- prep (weights + u/w/c0 + counters, one launch) ----
    prep_weights<<<dim3(32, 16, 4), dim3(32, 8)>>>(Wq, Wk, Wv, bv, bq, bk,
                                                   WqT, WkT, Wvh, bvp, u, w, c0);
    xpose_h<<<dim3(128, 16, 4), dim3(32, 8)>>>(x, xT);

    const size_t sXT = (size_t)4096 * 512;
    const size_t sV  = (size_t)512 * 4096;
    const size_t sAL = (size_t)4096 * 4096;
    const size_t sO  = (size_t)512 * 4096;

    // M split-K x4 with fused last-CTA reduce -> fp16 g_M (64 CTAs, one launch)
    gemm_h<4><<<dim3(4, 4, 4), 128, SMEM_TOTAL>>>(WkT, 1024, 256, WqT, 1024, 256,
                                                  Mp, 512, 262144, nullptr, 0, nullptr, 0, 256);
    // merged: v = Wv·xT + bv, y = xT·Mkq, rb/cb  (one 1152-CTA launch)
    gemm_dual<<<dim3(128, 1, 9), 128, SMEM_TOTAL>>>(Wvh, xT, M, v, y, bvp, u, w, c0, rb, cb);
    // aT[m][n] = sigmoid(x_m·y_n + rb[m] + cb[n])  (M=N=4096,K=512)
    gemm_h<3><<<dim3(32, 32, 4), 128, SMEM_TOTAL>>>(xT, 512, sXT, y, 512, sXT,
                                                    a, 4096, sAL, rb, 4096, cb, 4096, 512);
    // out[c][m] = v·aT  (M=512,N=4096,K=4096) fp32
    gemm_h<0><<<dim3(32, 4, 4), 128, SMEM_TOTAL>>>(v, 4096, sV, a, 4096, sAL,
                                                   out, 4096, sO, nullptr, 0, nullptr, 0, 4096);
}

// round 17
// speedup vs baseline: 1.0390x; 1.0390x over previous
#include <cuda_runtime.h>
#include <cuda_fp16.h>
#include <cstdint>
#include <cstddef>

// ---------------------------------------------------------------------------
// Sigmoid attention, algebraically refactored (R8-R14) + R17 (= R16 resubmit;
// R16 bench was an infra container failure, no kernel signal):
//   s[n,m] = y_n·x_m + u·x_m + w·x_n + c0,  y = x·(Wq^T Wk)  (O_CH contracts early)
// R16/17 = R14 with: (a) u/w/c0 computed as a prep z-slice, (b) M split-K
// reduce as a standalone 256-block bandwidth kernel, (c) xpose folded into the
// prep launch as z=4..7 slices.
// Chain: prep_all -> M-splitK -> reduce_M -> dual{v,y,rb/cb} -> alpha -> out.
// Hot GEMM mainloop unchanged (128x128 CTA, 4 warps of 64x64, 3-stage
// cp.async, ldmatrix.x4 double-buffered fragments, 2 CTA/SM).
// ---------------------------------------------------------------------------

#define BM 128
#define BN 128
#define STAGE 32768               // A tile 16KB + B tile 16KB
#define NSTAGE 3
#define SMEM_TOTAL (NSTAGE * STAGE)

// ------------------------------- scratch ------------------------------------
#define AL16 __align__(16)
static __device__ AL16 __half g_xT [(size_t)4*4096*512];    // xT[b][n][c]
static __device__ AL16 __half g_WqT[512*1024];              // Wq^T[c][o] (o pad 1000->1024)
static __device__ AL16 __half g_WkT[512*1024];              // Wk^T[c][o]
static __device__ AL16 __half g_Wv [512*512];               // Wv[c][c'] fp16
static __device__ AL16 float  g_Mp [4*512*512];             // split-K partials (fp32)
static __device__ AL16 __half g_M  [512*512];               // Mkq = Wk^T·Wq
static __device__ AL16 __half g_y  [(size_t)4*4096*512];    // y[b][n][c']
static __device__ AL16 __half g_v  [(size_t)4*512*4096];    // v[b][c][n]
static __device__ AL16 __half g_a  [(size_t)4*4096*4096];   // aT[b][m][n]
static __device__ float g_bv[512];
static __device__ float g_u[512], g_w[512], g_c0[1];
static __device__ float g_rb[4*4096], g_cb[4*4096];         // row/col bias for alpha

// ------------------------------- helpers ------------------------------------
__device__ __forceinline__ void ldsm_x4(uint32_t& r0, uint32_t& r1, uint32_t& r2, uint32_t& r3,
                                        uint32_t addr) {
    asm volatile("ldmatrix.sync.aligned.m8n8.x4.shared.b16 {%0,%1,%2,%3}, [%4];"
                 : "=r"(r0), "=r"(r1), "=r"(r2), "=r"(r3) : "r"(addr));
}

__device__ __forceinline__ void mma_fp16(float* d, const uint32_t* a, const uint32_t* b) {
    asm volatile(
        "mma.sync.aligned.m16n8k16.row.col.f32.f16.f16.f32 "
        "{%0,%1,%2,%3}, {%4,%5,%6,%7}, {%8,%9}, {%0,%1,%2,%3};\n"
        : "+f"(d[0]), "+f"(d[1]), "+f"(d[2]), "+f"(d[3])
        : "r"(a[0]), "r"(a[1]), "r"(a[2]), "r"(a[3]), "r"(b[0]), "r"(b[1]));
}

__device__ __forceinline__ float sigmoid_fast(float x) {
    float t;
    asm("tanh.approx.f32 %0, %1;" : "=f"(t) : "f"(0.5f * x));
    return 0.5f + 0.5f * t;
}

// ---------------------------- prep (one launch) ------------------------------
// grid (128, 16, 8), block (32, 8):
//   z=0 -> Wq^T (x<32) ; z=1 -> Wk^T (x<32) ; z=2 -> Wv fp16 + bv (x<32)
//   z=3 -> u/w/c0 (x<32) ; z=4..7 -> xpose batch z-4 (full x)
__global__ void prep_all(const float* __restrict__ x_, const float* __restrict__ Wq,
                         const float* __restrict__ Wk, const float* __restrict__ Wv,
                         const float* __restrict__ bv, const float* __restrict__ bq,
                         const float* __restrict__ bk,
                         __half* __restrict__ xT, __half* __restrict__ WqT,
                         __half* __restrict__ WkT, __half* __restrict__ Wvh,
                         float* __restrict__ bvp, float* __restrict__ u,
                         float* __restrict__ w, float* __restrict__ c0) {
    const int z = blockIdx.z;
    if (z >= 4) {
        // xpose: x[b][c][n] fp32 -> xT[b][n][c] fp16
        __shared__ float t[32][33];
        const int b = z - 4;
        const float* xb = x_ + (size_t)b * 512 * 4096;
        const int n0 = blockIdx.x * 32, c0_ = blockIdx.y * 32;
        const int tx = threadIdx.x, ty0 = threadIdx.y;
#pragma unroll
        for (int i = 0; i < 4; i++) {
            int ty = ty0 + i * 8;
            t[ty][tx] = xb[(size_t)(c0_ + ty) * 4096 + n0 + tx];
        }
        __syncthreads();
        const size_t ob = (size_t)b * 4096 * 512;
#pragma unroll
        for (int i = 0; i < 4; i++) {
            int ty = ty0 + i * 8;
            xT[ob + (size_t)(n0 + ty) * 512 + c0_ + tx] = __float2half_rn(t[tx][ty]);
        }
        return;
    }
    if (blockIdx.x >= 32) return;           // prep slices use x<32 only
    if (z < 2) {
        __shared__ float t[32][33];
        const float* W = z ? Wk : Wq;
        __half* WT = z ? WkT : WqT;
        const int r0 = blockIdx.x * 32, c0_ = blockIdx.y * 32;
        const int tx = threadIdx.x, ty0 = threadIdx.y;
#pragma unroll
        for (int i = 0; i < 4; i++) {
            int ty = ty0 + i * 8;
            int r = r0 + ty;
            t[ty][tx] = (r < 1000) ? W[(size_t)r * 512 + c0_ + tx] : 0.0f;
        }
        __syncthreads();
#pragma unroll
        for (int i = 0; i < 4; i++) {
            int ty = ty0 + i * 8;
            WT[(size_t)(c0_ + ty) * 1024 + r0 + tx] = __float2half_rn(t[tx][ty]);
        }
    } else if (z == 2) {
        // 512 blocks x 256 threads x 2 elements = 262144 = full Wv coverage
        int idx = (blockIdx.y * 32 + blockIdx.x) * 256 + threadIdx.y * 32 + threadIdx.x;
        Wvh[idx]          = __float2half_rn(Wv[idx]);
        Wvh[idx + 131072] = __float2half_rn(Wv[idx + 131072]);
        if (idx < 512) bvp[idx] = bv[idx];
    } else {
        // z == 3: u[c] = sum_o Wk[o][c]*bq[o] ; w[c] = sum_o Wq[o][c]*bk[o] ; c0 = bq.bk
        const int tid = threadIdx.y * 32 + threadIdx.x;   // 0..255
        if (blockIdx.y == 0) {
            __shared__ float su[16][16], sw[16][16];
            const int tx = tid & 15;            // channel-within-block
            const int og = tid >> 4;            // o-group 0..15
            const int c = blockIdx.x * 16 + tx;
            float au = 0.f, aw = 0.f;
            for (int o = og; o < 1000; o += 16) {
                au += Wk[(size_t)o * 512 + c] * bq[o];
                aw += Wq[(size_t)o * 512 + c] * bk[o];
            }
            su[og][tx] = au; sw[og][tx] = aw;
            __syncthreads();
            if (og == 0) {
                float a0 = 0.f, w0 = 0.f;
#pragma unroll
                for (int j = 0; j < 16; j++) { a0 += su[j][tx]; w0 += sw[j][tx]; }
                u[c] = a0; w[c] = w0;
            }
        } else if (blockIdx.y == 1 && blockIdx.x == 0) {
            if (tid < 32) {
                float s = 0.f;
                for (int o = tid; o < 1000; o += 32) s += bq[o] * bk[o];
#pragma unroll
                for (int off = 16; off > 0; off >>= 1) s += __shfl_xor_sync(0xFFFFFFFF, s, off);
                if (tid == 0) *c0 = s;
            }
        }
    }
}

// Reduce 4 split-K fp32 partials -> fp16 M. 256 blocks x 256 threads x 4 elems.
__global__ void reduce_M(const float* __restrict__ Mp, __half* __restrict__ M) {
    const int base = blockIdx.x * 1024 + threadIdx.x * 4;
    float4 s = *reinterpret_cast<const float4*>(Mp + base);
#pragma unroll
    for (int p = 1; p < 4; p++) {
        float4 t = *reinterpret_cast<const float4*>(Mp + p * 262144 + base);
        s.x += t.x; s.y += t.y; s.z += t.z; s.w += t.w;
    }
    __half2 h0 = __floats2half2_rn(s.x, s.y);
    __half2 h1 = __floats2half2_rn(s.z, s.w);
    *reinterpret_cast<uint2*>(M + base) =
        make_uint2(*reinterpret_cast<uint32_t*>(&h0), *reinterpret_cast<uint32_t*>(&h1));
}

// ------------------------- GEMM mainloop (macro body) ------------------------
#define GEMM_BODY(A_, lda_, B_, ldb_, K_)                                           \
    extern __shared__ __align__(1024) char smem[];                                  \
    const uint32_t sb = (uint32_t)__cvta_generic_to_shared(smem);                   \
    const int tid  = threadIdx.x;                                                   \
    const int lane = tid & 31;                                                      \
    const int w    = tid >> 5;                                                      \
    const int wm   = (w & 1) * 64;                                                  \
    const int wn   = (w >> 1) * 64;                                                 \
    const int g    = lane >> 2;                                                     \
    const int tg   = lane & 3;                                                      \
    const int T = (K_) / 64;                                                        \
    auto load_stage = [&](int t, int s) {                                           \
        const uint32_t st = sb + (uint32_t)(s * STAGE);                             \
        const int kc = t * 64;                                                      \
_Pragma("unroll")                                                                   \
        for (int i = 0; i < 16; i++) {                                              \
            int idx = tid + i * 128;                                                \
            int isB = idx >> 10;                                                    \
            int r   = (idx & 1023) >> 3;                                            \
            int c   = idx & 7;                                                      \
            uint32_t dst = st + (uint32_t)(isB * 16384 + r * 128 + ((c ^ (r & 7)) << 4)); \
            const __half* gp = (isB ? (B_) + (size_t)(n0 + r) * (ldb_)              \
                                    : (A_) + (size_t)(m0 + r) * (lda_)) + kc + c * 8; \
            asm volatile("cp.async.cg.shared.global [%0], [%1], 16;" :: "r"(dst), "l"(gp) : "memory"); \
        }                                                                           \
        asm volatile("cp.async.commit_group;" ::: "memory");                        \
    };                                                                              \
    float acc[4][8][4];                                                             \
_Pragma("unroll")                                                                   \
    for (int i = 0; i < 4; i++)                                                     \
_Pragma("unroll")                                                                   \
        for (int j = 0; j < 8; j++)                                                 \
_Pragma("unroll")                                                                   \
            for (int r = 0; r < 4; r++) acc[i][j][r] = 0.0f;                        \
    load_stage(0, 0);                                                               \
    load_stage(1, 1);                                                               \
    const int rowA = wm + (lane & 15);                                              \
    const int hiA  = lane >> 4;                                                     \
    const int rowB = wn + ((lane >> 4) << 3) + (lane & 7);                          \
    const int hiB  = (lane >> 3) & 1;                                               \
    for (int t = 0; t < T; t++) {                                                   \
        asm volatile("cp.async.wait_group 1;" ::: "memory");                        \
        __syncthreads();                                                            \
        const uint32_t st  = sb + (uint32_t)((t % NSTAGE) * STAGE);                 \
        const uint32_t stB = st + 16384;                                            \
        uint32_t af[2][4][4], bf[2][8][2];                                          \
        auto load_frags = [&](int ks, int buf) {                                    \
_Pragma("unroll")                                                                   \
            for (int im = 0; im < 4; im++) {                                        \
                const int r = rowA + im * 16;                                       \
                const int c = (ks * 2 + hiA) ^ (r & 7);                             \
                ldsm_x4(af[buf][im][0], af[buf][im][1], af[buf][im][2], af[buf][im][3], \
                        st + (uint32_t)(r * 128 + (c << 4)));                       \
            }                                                                       \
_Pragma("unroll")                                                                   \
            for (int jn = 0; jn < 4; jn++) {                                        \
                const int r = rowB + jn * 16;                                       \
                const int c = (ks * 2 + hiB) ^ (r & 7);                             \
                ldsm_x4(bf[buf][2*jn][0], bf[buf][2*jn][1], bf[buf][2*jn+1][0], bf[buf][2*jn+1][1], \
                        stB + (uint32_t)(r * 128 + (c << 4)));                      \
            }                                                                       \
        };                                                                          \
        load_frags(0, 0);                                                           \
        if (t + 2 < T) load_stage(t + 2, (t + 2) % NSTAGE);                         \
_Pragma("unroll")                                                                   \
        for (int ks = 0; ks < 4; ks++) {                                            \
            const int cur = ks & 1;                                                 \
            if (ks < 3) load_frags(ks + 1, cur ^ 1);                                \
_Pragma("unroll")                                                                   \
            for (int im = 0; im < 4; im++)                                          \
_Pragma("unroll")                                                                   \
                for (int in = 0; in < 8; in++)                                      \
                    mma_fp16(acc[im][in], af[cur][im], bf[cur][in]);                \
        }                                                                           \
    }

// ---------------------- hot GEMM (templated epilogue) ------------------------
// EPI: 0 = fp32 store (out / M split-K partials) ; 3 = sigmoid+biases (alpha)
template <int EPI>
__global__ __launch_bounds__(128, 2)
void gemm_h(const __half* __restrict__ Ag, int lda, size_t sA,
            const __half* __restrict__ Bg, int ldb, size_t sB,
            void* Dg, int ldd, size_t sD,
            const float* __restrict__ bias1, int s1,
            const float* __restrict__ bias2, int s2,
            int K) {
    const __half* A = Ag + (size_t)blockIdx.z * sA;
    const __half* B = Bg + (size_t)blockIdx.z * sB;
    const float* b1 = (EPI == 3) ? bias1 + (size_t)blockIdx.z * s1 : nullptr;
    const float* b2 = (EPI == 3) ? bias2 + (size_t)blockIdx.z * s2 : nullptr;
    const int m0 = blockIdx.y * BM;
    const int n0 = blockIdx.x * BN;

    GEMM_BODY(A, lda, B, ldb, K)

#pragma unroll
    for (int im = 0; im < 4; im++) {
        const int r0 = m0 + wm + im * 16 + g;
#pragma unroll
        for (int in = 0; in < 8; in++) {
            const int c = n0 + wn + in * 8 + 2 * tg;
#pragma unroll
            for (int h = 0; h < 2; h++) {
                const int r = r0 + h * 8;
                float vx = acc[im][in][2 * h];
                float vy = acc[im][in][2 * h + 1];
                if (EPI == 3) {
                    float bb = b1[r];
                    vx = sigmoid_fast(vx + bb + b2[c]);
                    vy = sigmoid_fast(vy + bb + b2[c + 1]);
                }
                if (EPI == 0) {
                    float* D = (float*)Dg + (size_t)blockIdx.z * sD + (size_t)r * ldd + c;
                    *reinterpret_cast<float2*>(D) = make_float2(vx, vy);
                } else {
                    __half* D = (__half*)Dg + (size_t)blockIdx.z * sD + (size_t)r * ldd + c;
                    *reinterpret_cast<__half2*>(D) = __floats2half2_rn(vx, vy);
                }
            }
        }
    }
}

// --------- merged v/y GEMM + rb/cb slice: one launch, runtime select ---------
// grid (128, 1, 9): z<4 -> v GEMM batch z; z in [4,8) -> y GEMM batch z-4;
//                   z==8 -> rb/cb computation (hidden under the GEMM slices).
__global__ __launch_bounds__(128, 2)
void gemm_dual(const __half* __restrict__ Wvh, const __half* __restrict__ xT,
               const __half* __restrict__ Mkq,
               __half* __restrict__ v, __half* __restrict__ y,
               const float* __restrict__ bvp,
               const float* __restrict__ u_, const float* __restrict__ w_,
               const float* __restrict__ c0_,
               float* __restrict__ rb, float* __restrict__ cb) {
    const size_t sXT = (size_t)4096 * 512;
    const int z = blockIdx.z;

    if (z == 8) {
        // rb[row] = u.x_row ; cb[row] = w.x_row + c0 ; 128 blocks x 128 rows
        extern __shared__ __align__(1024) float smemf[];
        float* su = smemf;            // 512 floats
        float* sw = smemf + 512;      // 512 floats
        const int tid = threadIdx.x;
        for (int i = tid; i < 512; i += 128) { su[i] = u_[i]; sw[i] = w_[i]; }
        __syncthreads();
        const float cc0 = *c0_;
        const int lane = tid & 31;
        const int warp = tid >> 5;
        for (int i = 0; i < 32; i++) {
            const int row = blockIdx.x * 128 + warp * 32 + i;
            const uint4* xr = reinterpret_cast<const uint4*>(xT + (size_t)row * 512);
            float au = 0.f, aw = 0.f;
#pragma unroll
            for (int j = 0; j < 2; j++) {
                const int v4 = lane + j * 32;          // uint4 index, 64 per row
                uint4 p = xr[v4];
                const __half2* h2 = reinterpret_cast<const __half2*>(&p);
                const int base = v4 * 8;
#pragma unroll
                for (int q = 0; q < 4; q++) {
                    float2 f = __half22float2(h2[q]);
                    au += su[base + 2*q] * f.x + su[base + 2*q + 1] * f.y;
                    aw += sw[base + 2*q] * f.x + sw[base + 2*q + 1] * f.y;
                }
            }
#pragma unroll
            for (int off = 16; off > 0; off >>= 1) {
                au += __shfl_xor_sync(0xFFFFFFFF, au, off);
                aw += __shfl_xor_sync(0xFFFFFFFF, aw, off);
            }
            if (lane == 0) { rb[row] = au; cb[row] = aw + cc0; }
        }
        return;
    }

    const int isV = (z < 4);
    const int b = isV ? z : z - 4;
    const int id = blockIdx.x;

    const __half* A;  const __half* B;  __half* D;
    int lda, ldb, ldd, m0, n0;
    const float* b1 = nullptr;
    if (isV) {         // v[c][n'] = Wv·xT + bv : M=512, N=4096, K=512; grid 4m x 32n
        A = Wvh; lda = 512;
        B = xT + (size_t)b * sXT; ldb = 512;
        D = v + (size_t)b * ((size_t)512 * 4096); ldd = 4096;
        m0 = (id >> 5) * BM;  n0 = (id & 31) * BN;
        b1 = bvp;
    } else {           // y[n][c'] = xT·Mkq : M=4096, N=512, K=512; grid 32m x 4n
        A = xT + (size_t)b * sXT; lda = 512;
        B = Mkq; ldb = 512;
        D = y + (size_t)b * sXT; ldd = 512;
        m0 = (id >> 2) * BM;  n0 = (id & 3) * BN;
    }

    GEMM_BODY(A, lda, B, ldb, 512)

#pragma unroll
    for (int im = 0; im < 4; im++) {
        const int r0 = m0 + wm + im * 16 + g;
#pragma unroll
        for (int in = 0; in < 8; in++) {
            const int c = n0 + wn + in * 8 + 2 * tg;
#pragma unroll
            for (int h = 0; h < 2; h++) {
                const int r = r0 + h * 8;
                float vx = acc[im][in][2 * h];
                float vy = acc[im][in][2 * h + 1];
                if (isV) { float bb = b1[r]; vx += bb; vy += bb; }
                __half* Dp = D + (size_t)r * ldd + c;
                *reinterpret_cast<__half2*>(Dp) = __floats2half2_rn(vx, vy);
            }
        }
    }
}

// ------------------------------- launch -------------------------------------
extern "C" void kernel_launch(void* const* d_in, const int* in_sizes, int n_in,
                              void* d_out, int out_size) {
    (void)in_sizes; (void)n_in; (void)out_size;
    const float* x  = (const float*)d_in[0];
    const float* Wq = (const float*)d_in[1];
    const float* bq = (const float*)d_in[2];
    const float* Wk = (const float*)d_in[3];
    const float* bk = (const float*)d_in[4];
    const float* Wv = (const float*)d_in[5];
    const float* bv = (const float*)d_in[6];
    float* out = (float*)d_out;

    __half *xT,*WqT,*WkT,*Wvh,*M,*y,*v,*a;
    float *Mp,*bvp,*u,*w,*c0,*rb,*cb;
    cudaGetSymbolAddress((void**)&xT,  g_xT);
    cudaGetSymbolAddress((void**)&WqT, g_WqT);
    cudaGetSymbolAddress((void**)&WkT, g_WkT);
    cudaGetSymbolAddress((void**)&Wvh, g_Wv);
    cudaGetSymbolAddress((void**)&Mp,  g_Mp);
    cudaGetSymbolAddress((void**)&M,   g_M);
    cudaGetSymbolAddress((void**)&y,   g_y);
    cudaGetSymbolAddress((void**)&v,   g_v);
    cudaGetSymbolAddress((void**)&a,   g_a);
    cudaGetSymbolAddress((void**)&bvp, g_bv);
    cudaGetSymbolAddress((void**)&u,   g_u);
    cudaGetSymbolAddress((void**)&w,   g_w);
    cudaGetSymbolAddress((void**)&c0,  g_c0);
    cudaGetSymbolAddress((void**)&rb,  g_rb);
    cudaGetSymbolAddress((void**)&cb,  g_cb);

    cudaFuncSetAttribute(gemm_h<0>, cudaFuncAttributeMaxDynamicSharedMemorySize, SMEM_TOTAL);
    cudaFuncSetAttribute(gemm_h<3>, cudaFuncAttributeMaxDynamicSharedMemorySize, SMEM_TOTAL);
    cudaFuncSetAttribute(gemm_dual, cudaFuncAttributeMaxDynamicSharedMemorySize, SMEM_TOTAL);

    // ---- prep: weights + u/w/c0 + x transpose, ONE launch ----
    prep_all<<<dim3(128, 16, 8), dim3(32, 8)>>>(x, Wq, Wk, Wv, bv, bq, bk,
                                                xT, WqT, WkT, Wvh, bvp, u, w, c0);

    const size_t sXT = (size_t)4096 * 512;
    const size_t sV  = (size_t)512 * 4096;
    const size_t sAL = (size_t)4096 * 4096;
    const size_t sO  = (size_t)512 * 4096;

    // Mpart[z] = Wk^T·Wq over K-chunk z (split-K x4: sA/sB=256 = K offset per z)
    gemm_h<0><<<dim3(4, 4, 4), 128, SMEM_TOTAL>>>(WkT, 1024, 256, WqT, 1024, 256,
                                                  Mp, 512, 262144, nullptr, 0, nullptr, 0, 256);
    // reduce Mpart -> fp16 M (pure bandwidth, 256 blocks)
    reduce_M<<<256, 256>>>(Mp, M);
    // merged: v = Wv·xT + bv, y = xT·Mkq, rb/cb  (one 1152-CTA launch)
    gemm_dual<<<dim3(128, 1, 9), 128, SMEM_TOTAL>>>(Wvh, xT, M, v, y, bvp, u, w, c0, rb, cb);
    // aT[m][n] = sigmoid(x_m·y_n + rb[m] + cb[n])  (M=N=4096,K=512)
    gemm_h<3><<<dim3(32, 32, 4), 128, SMEM_TOTAL>>>(xT, 512, sXT, y, 512, sXT,
                                                    a, 4096, sAL, rb, 4096, cb, 4096, 512);
    // out[c][m] = v·aT  (M=512,N=4096,K=4096) fp32
    gemm_h<0><<<dim3(32, 4, 4), 128, SMEM_TOTAL>>>(v, 4096, sV, a, 4096, sAL,
                                                   out, 4096, sO, nullptr, 0, nullptr, 0, 4096);
}